// round 6
// baseline (speedup 1.0000x reference)
#include <cuda_runtime.h>
#include <cstdint>
#include <cstddef>

// Problem constants (fixed shapes per reference)
#define B_N 131072
#define D_N 256
#define H_N 256
#define C_N 8

typedef unsigned long long ull;

// Per-expert routing scratch (device globals: no allocations allowed)
__device__ int g_cnt[C_N];
__device__ int g_rows[C_N * B_N];

// ---------------------------------------------------------------------------
// f32x2 packed-FMA helpers (sm_100+: fma.rn.f32x2 doubles fp32 FMA issue rate;
// ptxas never auto-fuses this — must come from PTX)
// ---------------------------------------------------------------------------
__device__ __forceinline__ ull pack2(float lo, float hi) {
    ull r; asm("mov.b64 %0, {%1, %2};" : "=l"(r) : "f"(lo), "f"(hi)); return r;
}
__device__ __forceinline__ void unpack2(ull v, float& lo, float& hi) {
    asm("mov.b64 {%0, %1}, %2;" : "=f"(lo), "=f"(hi) : "l"(v));
}
__device__ __forceinline__ void ffma2(ull& d, ull a, ull b) {
    asm("fma.rn.f32x2 %0, %1, %2, %0;" : "+l"(d) : "l"(a), "l"(b));
}

// Shared-memory layout (floats)
//  xs  : k-major transposed src tile [64][132]  (pad 132 keeps STS conflict-free
//        with the row-spread store mapping and 16B-aligned LDS.128 reads)
//  ws  : weight tile [64][256]
//  w2s : head weights [256][8]
#define XS_STRIDE 132
#define XS_FLOATS (64 * XS_STRIDE)          // 8448
#define WS_FLOATS (64 * 256)                // 16384
#define W2S_FLOATS (256 * 8)                // 2048
#define SMEM_CORE_FLOATS (XS_FLOATS + WS_FLOATS + W2S_FLOATS)  // 26880

#define SMEM1_BYTES (SMEM_CORE_FLOATS * 4 + (8 + 8 + 8 * 128) * 4)  // 111680
#define SMEM2_BYTES (SMEM_CORE_FLOATS * 4 + 128 * 4)                // 108032

// ---------------------------------------------------------------------------
// Shared GEMM mainloop: acc[128 rows x 256 cols] += src[rows, 256] @ W[256,256]
// 512 threads, 8x8 micro-tile per thread (warp = 8 rows, lane = 8 cols).
// GATHER=true pulls row indices from sidx (expert kernel).
// ---------------------------------------------------------------------------
template <bool GATHER>
__device__ __forceinline__ void gemm_mainloop(
    const float* __restrict__ src, const float* __restrict__ W,
    float* xs, float* ws, const int* sidx,
    int row0, int wr0, int c0, int tid, ull (&acc2)[8][4])
{
    for (int kb = 0; kb < 4; ++kb) {
        __syncthreads();
        // ---- load src tile [128 rows x 64 k] into k-major xs ----
        // lanes spread across rows at fixed kq -> conflict-free transposed STS
#pragma unroll
        for (int it = 0; it < 4; ++it) {
            int idx = it * 512 + tid;
            int kq  = idx >> 7;      // 0..15 (float4 along k)
            int rl  = idx & 127;     // local row
            int grow = GATHER ? sidx[rl] : (row0 + rl);
            float4 v = *(const float4*)(src + (size_t)grow * 256 + kb * 64 + kq * 4);
            float* dst = xs + (kq * 4) * XS_STRIDE + rl;
            dst[0 * XS_STRIDE] = v.x;
            dst[1 * XS_STRIDE] = v.y;
            dst[2 * XS_STRIDE] = v.z;
            dst[3 * XS_STRIDE] = v.w;
        }
        // ---- load W tile [64 k x 256 cols] ----
#pragma unroll
        for (int it = 0; it < 8; ++it) {
            int idx = it * 512 + tid;
            int r = idx >> 6;        // k within tile
            int q = idx & 63;        // float4 along cols
            *(float4*)(ws + r * 256 + q * 4) =
                *(const float4*)(W + (size_t)(kb * 64 + r) * 256 + q * 4);
        }
        __syncthreads();
        // ---- compute ----
#pragma unroll 8
        for (int k = 0; k < 64; ++k) {
            float4 a03 = *(const float4*)(xs + k * XS_STRIDE + wr0);      // broadcast
            float4 a47 = *(const float4*)(xs + k * XS_STRIDE + wr0 + 4);
            float4 b03 = *(const float4*)(ws + k * 256 + c0);
            float4 b47 = *(const float4*)(ws + k * 256 + c0 + 4);
            ull bb0 = pack2(b03.x, b03.y);
            ull bb1 = pack2(b03.z, b03.w);
            ull bb2 = pack2(b47.x, b47.y);
            ull bb3 = pack2(b47.z, b47.w);
            float av[8] = {a03.x, a03.y, a03.z, a03.w, a47.x, a47.y, a47.z, a47.w};
#pragma unroll
            for (int i = 0; i < 8; ++i) {
                ull aa = pack2(av[i], av[i]);
                ffma2(acc2[i][0], aa, bb0);
                ffma2(acc2[i][1], aa, bb1);
                ffma2(acc2[i][2], aa, bb2);
                ffma2(acc2[i][3], aa, bb3);
            }
        }
    }
}

// Per-row head-logits partial over this lane's 8-col chunk (reduced via shfl)
__device__ __forceinline__ void partial_logits(const float* w2s, const float h[8],
                                               int c0, float p[8])
{
#pragma unroll
    for (int c = 0; c < 8; ++c) p[c] = 0.f;
#pragma unroll
    for (int j = 0; j < 8; ++j) {
        float4 wlo = *(const float4*)(w2s + (c0 + j) * 8);
        float4 whi = *(const float4*)(w2s + (c0 + j) * 8 + 4);
        p[0] += h[j] * wlo.x; p[1] += h[j] * wlo.y;
        p[2] += h[j] * wlo.z; p[3] += h[j] * wlo.w;
        p[4] += h[j] * whi.x; p[5] += h[j] * whi.y;
        p[6] += h[j] * whi.z; p[7] += h[j] * whi.w;
    }
}

__device__ __forceinline__ void butterfly_reduce8(float p[8])
{
#pragma unroll
    for (int off = 16; off > 0; off >>= 1) {
#pragma unroll
        for (int c = 0; c < 8; ++c)
            p[c] += __shfl_xor_sync(0xffffffffu, p[c], off);
    }
}

// ---------------------------------------------------------------------------
// Kernel 0: reset expert counters
// ---------------------------------------------------------------------------
__global__ void reset_kernel()
{
    if (threadIdx.x < C_N) g_cnt[threadIdx.x] = 0;
}

// ---------------------------------------------------------------------------
// Kernel 1: root GEMM + relu + head logits + softmax routing + bucketing
// ---------------------------------------------------------------------------
__global__ void __launch_bounds__(512, 1) root_kernel(
    const float* __restrict__ x,  const float* __restrict__ W1,
    const float* __restrict__ b1, const float* __restrict__ W2,
    const float* __restrict__ b2, const float* __restrict__ tau,
    float* __restrict__ out_logits, float* __restrict__ out_h,
    float* __restrict__ out_depth)
{
    extern __shared__ float sm[];
    float* xs  = sm;
    float* ws  = sm + XS_FLOATS;
    float* w2s = ws + WS_FLOATS;
    int* scnt  = (int*)(w2s + W2S_FLOATS);
    int* sbase = scnt + 8;
    int* srows = sbase + 8;  // [8][128]

    const int tid  = threadIdx.x;
    const int lane = tid & 31;
    const int warp = tid >> 5;
    const int wr0  = warp * 8;
    const int c0   = lane * 8;
    const int row0 = blockIdx.x * 128;

    if (tid < 8) scnt[tid] = 0;
    // stage head weights (2048 floats / 512 threads)
    *(float4*)(w2s + tid * 4) = *(const float4*)(W2 + tid * 4);

    ull acc2[8][4];
#pragma unroll
    for (int i = 0; i < 8; ++i)
#pragma unroll
        for (int jp = 0; jp < 4; ++jp) acc2[i][jp] = 0ULL;

    gemm_mainloop<false>(x, W1, xs, ws, nullptr, row0, wr0, c0, tid, acc2);

    // epilogue
    float b1r[8];
    {
        float4 t0 = *(const float4*)(b1 + c0);
        float4 t1 = *(const float4*)(b1 + c0 + 4);
        b1r[0] = t0.x; b1r[1] = t0.y; b1r[2] = t0.z; b1r[3] = t0.w;
        b1r[4] = t1.x; b1r[5] = t1.y; b1r[6] = t1.z; b1r[7] = t1.w;
    }
    float b2r[8], taur[8];
    {
        float4 t0 = *(const float4*)(b2);     float4 t1 = *(const float4*)(b2 + 4);
        b2r[0] = t0.x; b2r[1] = t0.y; b2r[2] = t0.z; b2r[3] = t0.w;
        b2r[4] = t1.x; b2r[5] = t1.y; b2r[6] = t1.z; b2r[7] = t1.w;
        float4 u0 = *(const float4*)(tau);    float4 u1 = *(const float4*)(tau + 4);
        taur[0] = u0.x; taur[1] = u0.y; taur[2] = u0.z; taur[3] = u0.w;
        taur[4] = u1.x; taur[5] = u1.y; taur[6] = u1.z; taur[7] = u1.w;
    }

#pragma unroll
    for (int i = 0; i < 8; ++i) {
        float h[8];
        unpack2(acc2[i][0], h[0], h[1]);
        unpack2(acc2[i][1], h[2], h[3]);
        unpack2(acc2[i][2], h[4], h[5]);
        unpack2(acc2[i][3], h[6], h[7]);
#pragma unroll
        for (int j = 0; j < 8; ++j) {
            h[j] += b1r[j];
            h[j] = h[j] > 0.f ? h[j] : 0.f;
        }
        const int r = row0 + wr0 + i;
        *(float4*)(out_h + (size_t)r * 256 + c0)     = make_float4(h[0], h[1], h[2], h[3]);
        *(float4*)(out_h + (size_t)r * 256 + c0 + 4) = make_float4(h[4], h[5], h[6], h[7]);

        float p[8];
        partial_logits(w2s, h, c0, p);
        butterfly_reduce8(p);   // all lanes now hold the full logits of row i

        if (lane == i) {
            float lg[8];
#pragma unroll
            for (int c = 0; c < 8; ++c) lg[c] = p[c] + b2r[c];
            float m = lg[0];
#pragma unroll
            for (int c = 1; c < 8; ++c) m = fmaxf(m, lg[c]);
            float e[8]; float s = 0.f;
#pragma unroll
            for (int c = 0; c < 8; ++c) { e[c] = expf(lg[c] - m); s += e[c]; }
            const float inv = 1.0f / s;
            int best = -1; float bv = -1.0f;
#pragma unroll
            for (int c = 0; c < 8; ++c) {
                float pr = e[c] * inv;
                if (pr >= taur[c] && pr > bv) { bv = pr; best = c; }  // '>' = first-occurrence ties
            }
            *(float4*)(out_logits + (size_t)r * 8)     = make_float4(lg[0], lg[1], lg[2], lg[3]);
            *(float4*)(out_logits + (size_t)r * 8 + 4) = make_float4(lg[4], lg[5], lg[6], lg[7]);
            out_depth[r] = (best >= 0) ? 1.0f : 0.0f;
            if (best >= 0) {
                int pos = atomicAdd(&scnt[best], 1);
                srows[best * 128 + pos] = r;
            }
        }
    }

    // flush per-block buckets with 8 global atomics
    __syncthreads();
    if (tid < 8) sbase[tid] = atomicAdd(&g_cnt[tid], scnt[tid]);
    __syncthreads();
    for (int s2 = tid; s2 < 8 * 128; s2 += 512) {
        int e2 = s2 >> 7, i2 = s2 & 127;
        if (i2 < scnt[e2]) g_rows[e2 * B_N + sbase[e2] + i2] = srows[e2 * 128 + i2];
    }
}

// ---------------------------------------------------------------------------
// Kernel 2: per-expert gathered GEMM; overwrites routed rows of out_h/out_logits
// grid = (maxTiles=1024, C=8); empty tiles early-exit.
// ---------------------------------------------------------------------------
__global__ void __launch_bounds__(512, 1) expert_kernel(
    const float* __restrict__ Wc1, const float* __restrict__ bc1,
    const float* __restrict__ Wc2, const float* __restrict__ bc2,
    float* __restrict__ out_logits, float* __restrict__ out_h)
{
    const int c = blockIdx.y;
    const int cnt = g_cnt[c];
    const int start = blockIdx.x * 128;
    if (start >= cnt) return;
    const int n = min(128, cnt - start);

    extern __shared__ float sm[];
    float* xs  = sm;
    float* ws  = sm + XS_FLOATS;
    float* w2s = ws + WS_FLOATS;
    int* sidx  = (int*)(w2s + W2S_FLOATS);

    const int tid  = threadIdx.x;
    const int lane = tid & 31;
    const int warp = tid >> 5;
    const int wr0  = warp * 8;
    const int c0   = lane * 8;

    if (tid < 128) {
        int t = tid < n ? tid : (n - 1);   // pad tail with a valid row (never stored)
        sidx[tid] = g_rows[c * B_N + start + t];
    }
    *(float4*)(w2s + tid * 4) = *(const float4*)(Wc2 + c * (H_N * C_N) + tid * 4);

    ull acc2[8][4];
#pragma unroll
    for (int i = 0; i < 8; ++i)
#pragma unroll
        for (int jp = 0; jp < 4; ++jp) acc2[i][jp] = 0ULL;

    gemm_mainloop<true>(out_h, Wc1 + (size_t)c * H_N * H_N, xs, ws, sidx,
                        0, wr0, c0, tid, acc2);

    float b1r[8];
    {
        float4 t0 = *(const float4*)(bc1 + c * H_N + c0);
        float4 t1 = *(const float4*)(bc1 + c * H_N + c0 + 4);
        b1r[0] = t0.x; b1r[1] = t0.y; b1r[2] = t0.z; b1r[3] = t0.w;
        b1r[4] = t1.x; b1r[5] = t1.y; b1r[6] = t1.z; b1r[7] = t1.w;
    }
    float b2r[8];
    {
        float4 t0 = *(const float4*)(bc2 + c * 8);
        float4 t1 = *(const float4*)(bc2 + c * 8 + 4);
        b2r[0] = t0.x; b2r[1] = t0.y; b2r[2] = t0.z; b2r[3] = t0.w;
        b2r[4] = t1.x; b2r[5] = t1.y; b2r[6] = t1.z; b2r[7] = t1.w;
    }

#pragma unroll
    for (int i = 0; i < 8; ++i) {
        const bool valid = (wr0 + i) < n;
        const int r = sidx[wr0 + i];
        float h[8];
        unpack2(acc2[i][0], h[0], h[1]);
        unpack2(acc2[i][1], h[2], h[3]);
        unpack2(acc2[i][2], h[4], h[5]);
        unpack2(acc2[i][3], h[6], h[7]);
#pragma unroll
        for (int j = 0; j < 8; ++j) {
            h[j] += b1r[j];
            h[j] = h[j] > 0.f ? h[j] : 0.f;
        }
        if (valid) {
            *(float4*)(out_h + (size_t)r * 256 + c0)     = make_float4(h[0], h[1], h[2], h[3]);
            *(float4*)(out_h + (size_t)r * 256 + c0 + 4) = make_float4(h[4], h[5], h[6], h[7]);
        }
        float p[8];
        partial_logits(w2s, h, c0, p);
        butterfly_reduce8(p);
        if (lane == i && valid) {
            float lg[8];
#pragma unroll
            for (int cc = 0; cc < 8; ++cc) lg[cc] = p[cc] + b2r[cc];
            *(float4*)(out_logits + (size_t)r * 8)     = make_float4(lg[0], lg[1], lg[2], lg[3]);
            *(float4*)(out_logits + (size_t)r * 8 + 4) = make_float4(lg[4], lg[5], lg[6], lg[7]);
        }
    }
}

// ---------------------------------------------------------------------------
// Launcher (graph-capturable: kernel launches only)
// ---------------------------------------------------------------------------
extern "C" void kernel_launch(void* const* d_in, const int* in_sizes, int n_in,
                              void* d_out, int out_size)
{
    const float* x   = (const float*)d_in[0];
    const float* W1  = (const float*)d_in[1];
    const float* b1  = (const float*)d_in[2];
    const float* W2  = (const float*)d_in[3];
    const float* b2  = (const float*)d_in[4];
    const float* Wc1 = (const float*)d_in[5];
    const float* bc1 = (const float*)d_in[6];
    const float* Wc2 = (const float*)d_in[7];
    const float* bc2 = (const float*)d_in[8];
    const float* tau = (const float*)d_in[9];

    float* out        = (float*)d_out;
    float* out_logits = out;                          // [B, 8]
    float* out_h      = out + (size_t)B_N * C_N;      // [B, 256]
    float* out_depth  = out + (size_t)B_N * C_N + (size_t)B_N * H_N;  // [B]

    cudaFuncSetAttribute(root_kernel,   cudaFuncAttributeMaxDynamicSharedMemorySize, SMEM1_BYTES);
    cudaFuncSetAttribute(expert_kernel, cudaFuncAttributeMaxDynamicSharedMemorySize, SMEM2_BYTES);

    reset_kernel<<<1, 32>>>();
    root_kernel<<<B_N / 128, 512, SMEM1_BYTES>>>(
        x, W1, b1, W2, b2, tau, out_logits, out_h, out_depth);
    expert_kernel<<<dim3(B_N / 128, C_N), 512, SMEM2_BYTES>>>(
        Wc1, bc1, Wc2, bc2, out_logits, out_h);
}